// round 14
// baseline (speedup 1.0000x reference)
#include <cuda_runtime.h>
#include <cuda_fp16.h>

// Problem shape (fixed per dataset)
#define NN   50000
#define EE_CAP 1650512   // E + N self loops, with margin
#define D    128
#define DOUT 64
#define SCAN_B 256
#define CONV_BLOCKS 96   // 64 blocks W1/W2 + 32 blocks Wout

// ---- device scratch (no allocation allowed) ----
__device__ __half g_hh[NN * D];     // fp16 transformed features for the edge gather
__device__ float  g_x[NN * D];      // aggregation output / next layer input
__device__ float  g_ssrc[NN];       // h @ att_src
__device__ float  g_sdst[NN];       // h @ att_dst
__device__ __half g_w16a[D * D];    // W1 in fp16
__device__ __half g_w16b[D * D];    // W2 in fp16
__device__ __half g_w16o[D * DOUT]; // W_out in fp16
__device__ int    g_deg[NN];        // zeroed at static init; re-zeroed by scan portion
__device__ int    g_offs[NN + 1];
__device__ int    g_bsum[(NN + SCAN_B - 1) / SCAN_B];
__device__ int    g_cnt;            // scan publish counter  (reset by hmma_out)
__device__ int    g_cnt_rank;       // rank completion counter (reset by hmma_out)
__device__ int    g_rank[EE_CAP];   // per edge: (rank << 16) | dst
__device__ int    g_esrc[EE_CAP];   // CSR-by-dst: source node per edge

// packed f32x2 fma helpers
__device__ __forceinline__ void ffma2(unsigned long long& acc,
                                      unsigned long long a,
                                      unsigned long long b) {
    asm("fma.rn.f32x2 %0, %1, %2, %0;" : "+l"(acc) : "l"(a), "l"(b));
}
__device__ __forceinline__ unsigned long long dup2(float v) {
    unsigned long long r;
    asm("mov.b64 %0, {%1, %1};" : "=l"(r) : "f"(v));
    return r;
}

#define LDSM_X4T(b0, b1, b2, b3, addr) \
    asm volatile("ldmatrix.sync.aligned.m8n8.x4.trans.shared.b16 {%0,%1,%2,%3}, [%4];" \
                 : "=r"(b0), "=r"(b1), "=r"(b2), "=r"(b3) : "r"(addr))
#define MMA16816(d0, d1, d2, d3, a0, a1, a2, a3, b0, b1) \
    asm volatile("mma.sync.aligned.m16n8k16.row.col.f32.f16.f16.f32 " \
                 "{%0,%1,%2,%3}, {%4,%5,%6,%7}, {%8,%9}, {%0,%1,%2,%3};" \
                 : "+f"(d0), "+f"(d1), "+f"(d2), "+f"(d3) \
                 : "r"(a0), "r"(a1), "r"(a2), "r"(a3), "r"(b0), "r"(b1))

// ---------------------------------------------------------------- rank + W convert + scan (one launch)
__global__ void rank_scan_kernel(const int* __restrict__ ei, int E, int n,
                                 const float* __restrict__ W1f,
                                 const float* __restrict__ W2f,
                                 const float* __restrict__ Wof,
                                 int RB, int nb, int total) {
    if (blockIdx.x < 64) {
        int i = blockIdx.x * 256 + threadIdx.x;
        g_w16a[i] = __float2half_rn(W1f[i]);
        g_w16b[i] = __float2half_rn(W2f[i]);
        return;
    }
    if (blockIdx.x < CONV_BLOCKS) {
        int i = (blockIdx.x - 64) * 256 + threadIdx.x;
        if (i < D * DOUT) g_w16o[i] = __float2half_rn(Wof[i]);
        return;
    }
    if ((int)blockIdx.x < CONV_BLOCKS + RB) {
        // ---- rank portion ----
        int i0 = (((int)blockIdx.x - CONV_BLOCKS) * 256 + threadIdx.x) * 4;
        if (i0 + 3 < E && (E & 3) == 0) {
            int4 d4 = *(const int4*)&ei[E + i0];
            int4 r4;
            r4.x = (atomicAdd(&g_deg[d4.x], 1) << 16) | d4.x;
            r4.y = (atomicAdd(&g_deg[d4.y], 1) << 16) | d4.y;
            r4.z = (atomicAdd(&g_deg[d4.z], 1) << 16) | d4.z;
            r4.w = (atomicAdd(&g_deg[d4.w], 1) << 16) | d4.w;
            *(int4*)&g_rank[i0] = r4;
        } else {
#pragma unroll
            for (int u = 0; u < 4; u++) {
                int i = i0 + u;
                if (i < E) {
                    int d = ei[E + i];
                    g_rank[i] = (atomicAdd(&g_deg[d], 1) << 16) | d;
                } else if (i < E + n) {
                    int v = i - E;
                    g_rank[i] = (atomicAdd(&g_deg[v], 1) << 16) | v;
                }
            }
        }
        __syncthreads();
        if (threadIdx.x == 0) {
            __threadfence();
            atomicAdd(&g_cnt_rank, 1);
        }
        return;
    }

    // ---- scan portion ----
    __shared__ int ws[SCAN_B / 32];
    __shared__ int s_part;
    int sb = (int)blockIdx.x - CONV_BLOCKS - RB;
    int tid = threadIdx.x;
    int lane = tid & 31, wid = tid >> 5;

    if (tid == 0) {
        while (*(volatile int*)&g_cnt_rank < RB) { }
    }
    __syncthreads();
    __threadfence();

    int i = sb * SCAN_B + tid;
    int v = 0;
    if (i < n) {
        v = g_deg[i];
        g_deg[i] = 0;
    }
    int x = v;
#pragma unroll
    for (int o = 1; o < 32; o <<= 1) {
        int y = __shfl_up_sync(0xffffffffu, x, o);
        if (lane >= o) x += y;
    }
    if (lane == 31) ws[wid] = x;
    __syncthreads();
    int base = 0;
#pragma unroll
    for (int w = 0; w < SCAN_B / 32; w++)
        if (w < wid) base += ws[w];
    int ex = base + x - v;

    if (tid == SCAN_B - 1) {
        g_bsum[sb] = ex + v;
        __threadfence();
        atomicAdd(&g_cnt, 1);
    }
    if (tid == 0) {
        while (*(volatile int*)&g_cnt < nb) { }
    }
    __syncthreads();

    int part = 0;
    if (tid < sb) part = __ldcg(&g_bsum[tid]);
#pragma unroll
    for (int o = 16; o; o >>= 1) part += __shfl_xor_sync(0xffffffffu, part, o);
    if (lane == 0) ws[wid] = part;
    __syncthreads();
    if (tid == 0) {
        int p = 0;
#pragma unroll
        for (int w = 0; w < SCAN_B / 32; w++) p += ws[w];
        s_part = p;
    }
    __syncthreads();

    if (i < n) g_offs[i] = ex + s_part;
    if (i == 0) g_offs[n] = total;
}

// ---------------------------------------------------------------- HMMA GEMM core (GAT layers)
// 256 threads / 8 warps / 128 rows per block. Warp = 16 rows, all 128 cols.
// B loads: ldmatrix.x4.trans (two j-tiles per load), double-buffered so the
// next load is issued BEFORE the current pair of MMAs (latency overlapped).
#define XPAD 136
__device__ __forceinline__ void hmma_gemm_body(
    const float* __restrict__ X, const __half* __restrict__ W16,
    __half* __restrict__ hh_out,
    const float* __restrict__ asrc, const float* __restrict__ adst, int n,
    int rowbase, __half* smh) {
    __half* Xs = smh;                 // 128 x XPAD
    __half* Ws = smh + 128 * XPAD;    // 128 x XPAD
    int tid = threadIdx.x;
    int lane = tid & 31;
    int warp = tid >> 5;              // 0..7

    for (int i = tid; i < D * D; i += 256)
        Ws[(i >> 7) * XPAD + (i & 127)] = W16[i];
    for (int i = tid; i < 128 * D; i += 256) {
        int r = rowbase + (i >> 7);
        Xs[(i >> 7) * XPAD + (i & 127)] =
            (r < n) ? __float2half_rn(X[(size_t)r * D + (i & 127)]) : __half(0.f);
    }
    __syncthreads();

    unsigned xs_base = (unsigned)__cvta_generic_to_shared(Xs);
    unsigned ws_base = (unsigned)__cvta_generic_to_shared(Ws);
    int warpRow = warp * 16;

    unsigned a[8][4];
#pragma unroll
    for (int ka = 0; ka < 8; ka++) {
        unsigned addr = xs_base +
            ((warpRow + (lane & 15)) * XPAD + ka * 16 + (lane >> 4) * 8) * 2;
        asm volatile("ldmatrix.sync.aligned.m8n8.x4.shared.b16 {%0,%1,%2,%3}, [%4];"
                     : "=r"(a[ka][0]), "=r"(a[ka][1]), "=r"(a[ka][2]), "=r"(a[ka][3])
                     : "r"(addr));
    }

    int g = lane >> 2;
    int c2 = (lane & 3) * 2;
    int rowLo = rowbase + warpRow + g;
    int rowHi = rowLo + 8;

    // B fragment address for flat iteration it = j2*8 + ka
    unsigned wrow_off = (lane & 15) * XPAD + (lane >> 4) * 8;
#define BADDR(it) (ws_base + ((((it) & 7) * 16) * XPAD + ((it) >> 3) * 16 + wrow_off) * 2)

    float psL = 0.f, psH = 0.f, qdL = 0.f, qdH = 0.f;

    unsigned bb[2][4];
    LDSM_X4T(bb[0][0], bb[0][1], bb[0][2], bb[0][3], BADDR(0));

#pragma unroll
    for (int j2 = 0; j2 < 8; j2++) {
        float d0 = 0.f, d1 = 0.f, d2 = 0.f, d3 = 0.f;   // j-tile A
        float e0 = 0.f, e1 = 0.f, e2 = 0.f, e3 = 0.f;   // j-tile B
#pragma unroll
        for (int ka = 0; ka < 8; ka++) {
            int it = j2 * 8 + ka;
            int cur = it & 1;
            if (it + 1 < 64)
                LDSM_X4T(bb[cur ^ 1][0], bb[cur ^ 1][1], bb[cur ^ 1][2], bb[cur ^ 1][3],
                         BADDR(it + 1));
            MMA16816(d0, d1, d2, d3,
                     a[ka][0], a[ka][1], a[ka][2], a[ka][3], bb[cur][0], bb[cur][1]);
            MMA16816(e0, e1, e2, e3,
                     a[ka][0], a[ka][1], a[ka][2], a[ka][3], bb[cur][2], bb[cur][3]);
        }
        int colA = j2 * 16 + c2;
        int colB = colA + 8;
        float avA0 = asrc[colA], avA1 = asrc[colA + 1];
        float dvA0 = adst[colA], dvA1 = adst[colA + 1];
        float avB0 = asrc[colB], avB1 = asrc[colB + 1];
        float dvB0 = adst[colB], dvB1 = adst[colB + 1];
        psL += d0 * avA0 + d1 * avA1 + e0 * avB0 + e1 * avB1;
        psH += d2 * avA0 + d3 * avA1 + e2 * avB0 + e3 * avB1;
        qdL += d0 * dvA0 + d1 * dvA1 + e0 * dvB0 + e1 * dvB1;
        qdH += d2 * dvA0 + d3 * dvA1 + e2 * dvB0 + e3 * dvB1;
        if (rowLo < n) {
            *(__half2*)&hh_out[(size_t)rowLo * D + colA] = __floats2half2_rn(d0, d1);
            *(__half2*)&hh_out[(size_t)rowLo * D + colB] = __floats2half2_rn(e0, e1);
        }
        if (rowHi < n) {
            *(__half2*)&hh_out[(size_t)rowHi * D + colA] = __floats2half2_rn(d2, d3);
            *(__half2*)&hh_out[(size_t)rowHi * D + colB] = __floats2half2_rn(e2, e3);
        }
    }
#undef BADDR

    psL += __shfl_xor_sync(0xffffffffu, psL, 1);
    psL += __shfl_xor_sync(0xffffffffu, psL, 2);
    psH += __shfl_xor_sync(0xffffffffu, psH, 1);
    psH += __shfl_xor_sync(0xffffffffu, psH, 2);
    qdL += __shfl_xor_sync(0xffffffffu, qdL, 1);
    qdL += __shfl_xor_sync(0xffffffffu, qdL, 2);
    qdH += __shfl_xor_sync(0xffffffffu, qdH, 1);
    qdH += __shfl_xor_sync(0xffffffffu, qdH, 2);
    if ((lane & 3) == 0) {
        if (rowLo < n) { g_ssrc[rowLo] = psL; g_sdst[rowLo] = qdL; }
        if (rowHi < n) { g_ssrc[rowHi] = psH; g_sdst[rowHi] = qdH; }
    }
}

// ---- layer-1: GEMM blocks + placement blocks in one launch ----
#define PLACE_EPT 4
__global__ void __launch_bounds__(256) hmma_gemm_place_kernel(
    const float* __restrict__ X, const __half* __restrict__ W16,
    __half* __restrict__ hh_out,
    const float* __restrict__ asrc, const float* __restrict__ adst, int n,
    const int* __restrict__ ei, int E, int hmma_grid) {
    if ((int)blockIdx.x >= hmma_grid) {
        int pb = (int)blockIdx.x - hmma_grid;
        int i0 = (pb * 256 + (int)threadIdx.x) * PLACE_EPT;
#pragma unroll
        for (int q = 0; q < PLACE_EPT; q += 4) {
            int ib = i0 + q;
            if (ib + 3 < E && (E & 3) == 0) {
                int4 s4 = *(const int4*)&ei[ib];
                int4 r4 = *(const int4*)&g_rank[ib];
                g_esrc[g_offs[r4.x & 0xFFFF] + (r4.x >> 16)] = s4.x;
                g_esrc[g_offs[r4.y & 0xFFFF] + (r4.y >> 16)] = s4.y;
                g_esrc[g_offs[r4.z & 0xFFFF] + (r4.z >> 16)] = s4.z;
                g_esrc[g_offs[r4.w & 0xFFFF] + (r4.w >> 16)] = s4.w;
            } else {
#pragma unroll
                for (int u = 0; u < 4; u++) {
                    int i = ib + u;
                    if (i < E) {
                        int pk = g_rank[i];
                        g_esrc[g_offs[pk & 0xFFFF] + (pk >> 16)] = ei[i];
                    } else if (i < E + n) {
                        int pk = g_rank[i];
                        g_esrc[g_offs[pk & 0xFFFF] + (pk >> 16)] = i - E;
                    }
                }
            }
        }
        return;
    }
    extern __shared__ __half smh[];
    hmma_gemm_body(X, W16, hh_out, asrc, adst, n, blockIdx.x * 128, smh);
}

__global__ void __launch_bounds__(256) hmma_gemm_kernel(
    const float* __restrict__ X, const __half* __restrict__ W16,
    __half* __restrict__ hh_out,
    const float* __restrict__ asrc, const float* __restrict__ adst, int n) {
    extern __shared__ __half smh[];
    hmma_gemm_body(X, W16, hh_out, asrc, adst, n, blockIdx.x * 128, smh);
}

// ---------------------------------------------------------------- HMMA output GEMM (+ counter reset)
// 128 threads / 64 rows / pipelined x4.trans B loads over 4 j2-tiles.
#define WPAD 72
__global__ void __launch_bounds__(128) hmma_out_kernel(
    const float* __restrict__ X, const __half* __restrict__ Wo16,
    const float* __restrict__ bias, float* __restrict__ Y, int n) {
    extern __shared__ __half smh[];
    __half* Xs = smh;                 // 64 x XPAD
    __half* Ws = smh + 64 * XPAD;     // 128 x WPAD
    int tid = threadIdx.x;
    int lane = tid & 31;
    int warp = tid >> 5;
    int rowbase = blockIdx.x * 64;

    if (blockIdx.x == 0 && tid == 0) {
        g_cnt = 0;
        g_cnt_rank = 0;
    }

    for (int i = tid; i < D * DOUT; i += 128)
        Ws[(i / DOUT) * WPAD + (i % DOUT)] = Wo16[i];
    for (int i = tid; i < 64 * D; i += 128) {
        int r = rowbase + (i >> 7);
        Xs[(i >> 7) * XPAD + (i & 127)] =
            (r < n) ? __float2half_rn(X[(size_t)r * D + (i & 127)]) : __half(0.f);
    }
    __syncthreads();

    unsigned xs_base = (unsigned)__cvta_generic_to_shared(Xs);
    unsigned ws_base = (unsigned)__cvta_generic_to_shared(Ws);
    int warpRow = warp * 16;

    unsigned a[8][4];
#pragma unroll
    for (int ka = 0; ka < 8; ka++) {
        unsigned addr = xs_base +
            ((warpRow + (lane & 15)) * XPAD + ka * 16 + (lane >> 4) * 8) * 2;
        asm volatile("ldmatrix.sync.aligned.m8n8.x4.shared.b16 {%0,%1,%2,%3}, [%4];"
                     : "=r"(a[ka][0]), "=r"(a[ka][1]), "=r"(a[ka][2]), "=r"(a[ka][3])
                     : "r"(addr));
    }

    int g = lane >> 2;
    int c2 = (lane & 3) * 2;
    int rowLo = rowbase + warpRow + g;
    int rowHi = rowLo + 8;

    unsigned wrow_off = (lane & 15) * WPAD + (lane >> 4) * 8;
#define BADDR_O(it) (ws_base + ((((it) & 7) * 16) * WPAD + ((it) >> 3) * 16 + wrow_off) * 2)

    unsigned bb[2][4];
    LDSM_X4T(bb[0][0], bb[0][1], bb[0][2], bb[0][3], BADDR_O(0));

#pragma unroll
    for (int j2 = 0; j2 < 4; j2++) {
        float d0 = 0.f, d1 = 0.f, d2 = 0.f, d3 = 0.f;
        float e0 = 0.f, e1 = 0.f, e2 = 0.f, e3 = 0.f;
#pragma unroll
        for (int ka = 0; ka < 8; ka++) {
            int it = j2 * 8 + ka;
            int cur = it & 1;
            if (it + 1 < 32)
                LDSM_X4T(bb[cur ^ 1][0], bb[cur ^ 1][1], bb[cur ^ 1][2], bb[cur ^ 1][3],
                         BADDR_O(it + 1));
            MMA16816(d0, d1, d2, d3,
                     a[ka][0], a[ka][1], a[ka][2], a[ka][3], bb[cur][0], bb[cur][1]);
            MMA16816(e0, e1, e2, e3,
                     a[ka][0], a[ka][1], a[ka][2], a[ka][3], bb[cur][2], bb[cur][3]);
        }
        int colA = j2 * 16 + c2;
        int colB = colA + 8;
        float bA0 = bias[colA], bA1 = bias[colA + 1];
        float bB0 = bias[colB], bB1 = bias[colB + 1];
        if (rowLo < n) {
            *(float2*)&Y[(size_t)rowLo * DOUT + colA] = make_float2(d0 + bA0, d1 + bA1);
            *(float2*)&Y[(size_t)rowLo * DOUT + colB] = make_float2(e0 + bB0, e1 + bB1);
        }
        if (rowHi < n) {
            *(float2*)&Y[(size_t)rowHi * DOUT + colA] = make_float2(d2 + bA0, d3 + bA1);
            *(float2*)&Y[(size_t)rowHi * DOUT + colB] = make_float2(e2 + bB0, e3 + bB1);
        }
    }
#undef BADDR_O
}

// ---------------------------------------------------------------- fused alpha + aggregation
#define CH 64
__global__ void __launch_bounds__(256, 6) gat_edge_kernel(
    const __half* __restrict__ hh, const float* __restrict__ bias,
    float* __restrict__ out, int n, int do_relu) {
    __shared__ float2 stage[8][CH];
    int gt = blockIdx.x * blockDim.x + threadIdx.x;
    int node = gt >> 5, lane = gt & 31;
    int wslot = (threadIdx.x >> 5);
    if (node >= n) return;

    int beg = g_offs[node];
    int end = g_offs[node + 1];
    float sd = g_sdst[node];
    int h = lane >> 4;
    int lane8 = lane & 15;
    const char* hbase = (const char*)hh + lane8 * 16;

    float denom = 0.f;
    unsigned long long acc0 = 0ull, acc1 = 0ull, acc2 = 0ull, acc3 = 0ull;

    for (int cb = beg; cb < end; cb += CH) {
        int m = min(CH, end - cb);
        for (int t = lane; t < m; t += 32) {
            int s = g_esrc[cb + t];
            float ex = __expf(fmaxf(g_ssrc[s] + sd, 0.f));
            denom += ex;
            stage[wslot][t] = make_float2(__int_as_float(s << 8), ex);
        }
        if ((m & 1) && lane == 0)
            stage[wslot][m] = make_float2(stage[wslot][0].x, 0.f);
        __syncwarp();

        int mp = (m + 1) & ~1;
        int k = 0;
        for (; k + 8 <= mp; k += 8) {
            float2 p0 = stage[wslot][k + 0 + h];
            float2 p1 = stage[wslot][k + 2 + h];
            float2 p2 = stage[wslot][k + 4 + h];
            float2 p3 = stage[wslot][k + 6 + h];
            uint4 v0 = *(const uint4*)(hbase + (unsigned)__float_as_int(p0.x));
            uint4 v1 = *(const uint4*)(hbase + (unsigned)__float_as_int(p1.x));
            uint4 v2 = *(const uint4*)(hbase + (unsigned)__float_as_int(p2.x));
            uint4 v3 = *(const uint4*)(hbase + (unsigned)__float_as_int(p3.x));
#define EDGE_STEP(vv, ww) do { \
                unsigned long long w_ = dup2(ww); \
                float2 a0_ = __half22float2(*(__half2*)&(vv).x); \
                float2 a1_ = __half22float2(*(__half2*)&(vv).y); \
                float2 a2_ = __half22float2(*(__half2*)&(vv).z); \
                float2 a3_ = __half22float2(*(__half2*)&(vv).w); \
                ffma2(acc0, w_, *(unsigned long long*)&a0_); \
                ffma2(acc1, w_, *(unsigned long long*)&a1_); \
                ffma2(acc2, w_, *(unsigned long long*)&a2_); \
                ffma2(acc3, w_, *(unsigned long long*)&a3_); \
            } while (0)
            EDGE_STEP(v0, p0.y);
            EDGE_STEP(v1, p1.y);
            EDGE_STEP(v2, p2.y);
            EDGE_STEP(v3, p3.y);
        }
        for (; k < mp; k += 2) {
            float2 p = stage[wslot][k + h];
            uint4 v = *(const uint4*)(hbase + (unsigned)__float_as_int(p.x));
            EDGE_STEP(v, p.y);
        }
#undef EDGE_STEP
        __syncwarp();
    }

#pragma unroll
    for (int o = 16; o; o >>= 1) denom += __shfl_xor_sync(0xffffffffu, denom, o);
    float inv = 1.f / denom;

    float2 f0 = *(float2*)&acc0;
    float2 f1 = *(float2*)&acc1;
    float2 f2 = *(float2*)&acc2;
    float2 f3 = *(float2*)&acc3;
    f0.x += __shfl_xor_sync(0xffffffffu, f0.x, 16);
    f0.y += __shfl_xor_sync(0xffffffffu, f0.y, 16);
    f1.x += __shfl_xor_sync(0xffffffffu, f1.x, 16);
    f1.y += __shfl_xor_sync(0xffffffffu, f1.y, 16);
    f2.x += __shfl_xor_sync(0xffffffffu, f2.x, 16);
    f2.y += __shfl_xor_sync(0xffffffffu, f2.y, 16);
    f3.x += __shfl_xor_sync(0xffffffffu, f3.x, 16);
    f3.y += __shfl_xor_sync(0xffffffffu, f3.y, 16);

    if (h == 0) {
        int fb = lane8 * 8;
        float4 b0 = *(const float4*)&bias[fb];
        float4 b1 = *(const float4*)&bias[fb + 4];
        float4 o0, o1;
        o0.x = f0.x * inv + b0.x;
        o0.y = f0.y * inv + b0.y;
        o0.z = f1.x * inv + b0.z;
        o0.w = f1.y * inv + b0.w;
        o1.x = f2.x * inv + b1.x;
        o1.y = f2.y * inv + b1.y;
        o1.z = f3.x * inv + b1.z;
        o1.w = f3.y * inv + b1.w;
        if (do_relu) {
            o0.x = fmaxf(o0.x, 0.f); o0.y = fmaxf(o0.y, 0.f);
            o0.z = fmaxf(o0.z, 0.f); o0.w = fmaxf(o0.w, 0.f);
            o1.x = fmaxf(o1.x, 0.f); o1.y = fmaxf(o1.y, 0.f);
            o1.z = fmaxf(o1.z, 0.f); o1.w = fmaxf(o1.w, 0.f);
        }
        *(float4*)&out[(size_t)node * D + fb] = o0;
        *(float4*)&out[(size_t)node * D + fb + 4] = o1;
    }
}

// ---------------------------------------------------------------- launch
extern "C" void kernel_launch(void* const* d_in, const int* in_sizes, int n_in,
                              void* d_out, int out_size) {
    const float* node_x = (const float*)d_in[0];
    const int*   ei     = (const int*)d_in[1];
    const float* W1     = (const float*)d_in[2];
    const float* as1    = (const float*)d_in[3];
    const float* ad1    = (const float*)d_in[4];
    const float* b1     = (const float*)d_in[5];
    const float* W2     = (const float*)d_in[6];
    const float* as2    = (const float*)d_in[7];
    const float* ad2    = (const float*)d_in[8];
    const float* b2     = (const float*)d_in[9];
    const float* Wout   = (const float*)d_in[10];
    const float* bout   = (const float*)d_in[11];
    float* out = (float*)d_out;

    int n = in_sizes[0] / D;       // 50000
    int E = in_sizes[1] / 2;       // 1600000

    float* x_ptr;
    __half *hh_ptr, *w16a_ptr, *w16b_ptr, *w16o_ptr;
    cudaGetSymbolAddress((void**)&x_ptr, g_x);
    cudaGetSymbolAddress((void**)&hh_ptr, g_hh);
    cudaGetSymbolAddress((void**)&w16a_ptr, g_w16a);
    cudaGetSymbolAddress((void**)&w16b_ptr, g_w16b);
    cudaGetSymbolAddress((void**)&w16o_ptr, g_w16o);

    const int SMEM_HMMA = (128 * XPAD + 128 * XPAD) * (int)sizeof(__half); // ~68 KB
    const int SMEM_OUT  = (64 * XPAD + 128 * WPAD) * (int)sizeof(__half);  // ~35 KB
    cudaFuncSetAttribute(hmma_gemm_place_kernel, cudaFuncAttributeMaxDynamicSharedMemorySize, SMEM_HMMA);
    cudaFuncSetAttribute(hmma_gemm_kernel, cudaFuncAttributeMaxDynamicSharedMemorySize, SMEM_HMMA);
    cudaFuncSetAttribute(hmma_out_kernel, cudaFuncAttributeMaxDynamicSharedMemorySize, SMEM_OUT);

    int tot = E + n;
    int nb = (n + SCAN_B - 1) / SCAN_B;
    int RB = (tot + 1023) / 1024;
    int agg_grid = (n * 32 + 255) / 256;
    int hmma_grid = (n + 127) / 128;
    int out_grid = (n + 63) / 64;
    int place_blocks = (tot + 256 * PLACE_EPT - 1) / (256 * PLACE_EPT);

    // CSR rank + W conversion + scan, one launch
    rank_scan_kernel<<<CONV_BLOCKS + RB + nb, 256>>>(ei, E, n, W1, W2, Wout, RB, nb, tot);

    // layer-1 GEMM + placement merged
    hmma_gemm_place_kernel<<<hmma_grid + place_blocks, 256, SMEM_HMMA>>>(
        node_x, w16a_ptr, hh_ptr, as1, ad1, n, ei, E, hmma_grid);
    gat_edge_kernel<<<agg_grid, 256>>>(hh_ptr, b1, x_ptr, n, 1);

    // layer 2
    hmma_gemm_kernel<<<hmma_grid, 256, SMEM_HMMA>>>(x_ptr, w16b_ptr, hh_ptr, as2, ad2, n);
    gat_edge_kernel<<<agg_grid, 256>>>(hh_ptr, b2, x_ptr, n, 0);

    // output linear (HMMA) + counter reset for next replay
    hmma_out_kernel<<<out_grid, 128, SMEM_OUT>>>(x_ptr, w16o_ptr, bout, out, n);
}

// round 15
// speedup vs baseline: 1.1069x; 1.1069x over previous
#include <cuda_runtime.h>
#include <cuda_fp16.h>

// Problem shape (fixed per dataset)
#define NN   50000
#define EE_CAP 1650512   // E + N self loops, with margin
#define D    128
#define DOUT 64
#define SCAN_B 256
#define NXB  1563        // node_x fp32->fp16 convert blocks (NN*D/4 f4 / 1024)
#define CONV_BLOCKS (96 + NXB)

// ---- device scratch (no allocation allowed) ----
__device__ __half g_hh[NN * D];     // fp16 transformed features for the edge gather
__device__ __half g_xh[NN * D];     // fp16 aggregation output / next GEMM input
__device__ __half g_nx16[NN * D];   // fp16 copy of node_x
__device__ float  g_ssrc[NN];       // h @ att_src
__device__ float  g_sdst[NN];       // h @ att_dst
__device__ __half g_w16a[D * D];    // W1 in fp16
__device__ __half g_w16b[D * D];    // W2 in fp16
__device__ __half g_w16o[D * DOUT]; // W_out in fp16
__device__ int    g_deg[NN];        // zeroed at static init; re-zeroed by scan portion
__device__ int    g_offs[NN + 1];
__device__ int    g_bsum[(NN + SCAN_B - 1) / SCAN_B];
__device__ int    g_cnt;            // scan publish counter  (reset by hmma_out)
__device__ int    g_cnt_rank;       // rank completion counter (reset by hmma_out)
__device__ int    g_rank[EE_CAP];   // per edge: (rank << 16) | dst
__device__ int    g_esrc[EE_CAP];   // CSR-by-dst: source node per edge

// packed f32x2 fma helpers
__device__ __forceinline__ void ffma2(unsigned long long& acc,
                                      unsigned long long a,
                                      unsigned long long b) {
    asm("fma.rn.f32x2 %0, %1, %2, %0;" : "+l"(acc) : "l"(a), "l"(b));
}
__device__ __forceinline__ unsigned long long dup2(float v) {
    unsigned long long r;
    asm("mov.b64 %0, {%1, %1};" : "=l"(r) : "f"(v));
    return r;
}
__device__ __forceinline__ void cp16(unsigned dst, const void* src) {
    asm volatile("cp.async.cg.shared.global [%0], [%1], 16;" :: "r"(dst), "l"(src));
}

#define LDSM_X4T(b0, b1, b2, b3, addr) \
    asm volatile("ldmatrix.sync.aligned.m8n8.x4.trans.shared.b16 {%0,%1,%2,%3}, [%4];" \
                 : "=r"(b0), "=r"(b1), "=r"(b2), "=r"(b3) : "r"(addr))
#define MMA16816(d0, d1, d2, d3, a0, a1, a2, a3, b0, b1) \
    asm volatile("mma.sync.aligned.m16n8k16.row.col.f32.f16.f16.f32 " \
                 "{%0,%1,%2,%3}, {%4,%5,%6,%7}, {%8,%9}, {%0,%1,%2,%3};" \
                 : "+f"(d0), "+f"(d1), "+f"(d2), "+f"(d3) \
                 : "r"(a0), "r"(a1), "r"(a2), "r"(a3), "r"(b0), "r"(b1))

// ---------------------------------------------------------------- rank + W/X convert + scan
// Blocks [0,64): W1/W2. [64,96): Wout. [96, 96+NXB): node_x -> fp16.
// [CONV, CONV+RB): per-edge rank (one atomic, also the histogram).
// [CONV+RB, ...): scan (spins on rank counter; re-zeroes g_deg).
__global__ void rank_scan_kernel(const int* __restrict__ ei, int E, int n,
                                 const float* __restrict__ W1f,
                                 const float* __restrict__ W2f,
                                 const float* __restrict__ Wof,
                                 const float* __restrict__ Xf, int nelem4,
                                 int RB, int nb, int total) {
    if (blockIdx.x < 64) {
        int i = blockIdx.x * 256 + threadIdx.x;
        g_w16a[i] = __float2half_rn(W1f[i]);
        g_w16b[i] = __float2half_rn(W2f[i]);
        return;
    }
    if (blockIdx.x < 96) {
        int i = (blockIdx.x - 64) * 256 + threadIdx.x;
        if (i < D * DOUT) g_w16o[i] = __float2half_rn(Wof[i]);
        return;
    }
    if ((int)blockIdx.x < CONV_BLOCKS) {
        // node_x fp32 -> fp16 (coalesced float4 -> uint2)
        int f4 = ((int)blockIdx.x - 96) * 1024 + threadIdx.x;
#pragma unroll
        for (int q = 0; q < 4; q++) {
            int idx = f4 + q * 256;
            if (idx < nelem4) {
                float4 v = ((const float4*)Xf)[idx];
                __half2 h0 = __floats2half2_rn(v.x, v.y);
                __half2 h1 = __floats2half2_rn(v.z, v.w);
                uint2 pk;
                pk.x = *(unsigned*)&h0;
                pk.y = *(unsigned*)&h1;
                ((uint2*)g_nx16)[idx] = pk;
            }
        }
        return;
    }
    if ((int)blockIdx.x < CONV_BLOCKS + RB) {
        // ---- rank portion ----
        int i0 = (((int)blockIdx.x - CONV_BLOCKS) * 256 + threadIdx.x) * 4;
        if (i0 + 3 < E && (E & 3) == 0) {
            int4 d4 = *(const int4*)&ei[E + i0];
            int4 r4;
            r4.x = (atomicAdd(&g_deg[d4.x], 1) << 16) | d4.x;
            r4.y = (atomicAdd(&g_deg[d4.y], 1) << 16) | d4.y;
            r4.z = (atomicAdd(&g_deg[d4.z], 1) << 16) | d4.z;
            r4.w = (atomicAdd(&g_deg[d4.w], 1) << 16) | d4.w;
            *(int4*)&g_rank[i0] = r4;
        } else {
#pragma unroll
            for (int u = 0; u < 4; u++) {
                int i = i0 + u;
                if (i < E) {
                    int d = ei[E + i];
                    g_rank[i] = (atomicAdd(&g_deg[d], 1) << 16) | d;
                } else if (i < E + n) {
                    int v = i - E;
                    g_rank[i] = (atomicAdd(&g_deg[v], 1) << 16) | v;
                }
            }
        }
        __syncthreads();
        if (threadIdx.x == 0) {
            __threadfence();
            atomicAdd(&g_cnt_rank, 1);
        }
        return;
    }

    // ---- scan portion ----
    __shared__ int ws[SCAN_B / 32];
    __shared__ int s_part;
    int sb = (int)blockIdx.x - CONV_BLOCKS - RB;
    int tid = threadIdx.x;
    int lane = tid & 31, wid = tid >> 5;

    if (tid == 0) {
        while (*(volatile int*)&g_cnt_rank < RB) { }
    }
    __syncthreads();
    __threadfence();

    int i = sb * SCAN_B + tid;
    int v = 0;
    if (i < n) {
        v = g_deg[i];
        g_deg[i] = 0;
    }
    int x = v;
#pragma unroll
    for (int o = 1; o < 32; o <<= 1) {
        int y = __shfl_up_sync(0xffffffffu, x, o);
        if (lane >= o) x += y;
    }
    if (lane == 31) ws[wid] = x;
    __syncthreads();
    int base = 0;
#pragma unroll
    for (int w = 0; w < SCAN_B / 32; w++)
        if (w < wid) base += ws[w];
    int ex = base + x - v;

    if (tid == SCAN_B - 1) {
        g_bsum[sb] = ex + v;
        __threadfence();
        atomicAdd(&g_cnt, 1);
    }
    if (tid == 0) {
        while (*(volatile int*)&g_cnt < nb) { }
    }
    __syncthreads();

    int part = 0;
    if (tid < sb) part = __ldcg(&g_bsum[tid]);
#pragma unroll
    for (int o = 16; o; o >>= 1) part += __shfl_xor_sync(0xffffffffu, part, o);
    if (lane == 0) ws[wid] = part;
    __syncthreads();
    if (tid == 0) {
        int p = 0;
#pragma unroll
        for (int w = 0; w < SCAN_B / 32; w++) p += ws[w];
        s_part = p;
    }
    __syncthreads();

    if (i < n) g_offs[i] = ex + s_part;
    if (i == 0) g_offs[n] = total;
}

// ---------------------------------------------------------------- HMMA GEMM core (GAT layers)
// 256 threads / 8 warps / 128 rows. fp16 X input via cp.async (no CVT in prologue).
#define XPAD 136
__device__ __forceinline__ void hmma_gemm_body(
    const __half* __restrict__ Xh, const __half* __restrict__ W16,
    __half* __restrict__ hh_out,
    const float* __restrict__ asrc, const float* __restrict__ adst, int n,
    int rowbase, __half* smh) {
    __half* Xs = smh;                 // 128 x XPAD
    __half* Ws = smh + 128 * XPAD;    // 128 x XPAD
    int tid = threadIdx.x;
    int lane = tid & 31;
    int warp = tid >> 5;              // 0..7

    unsigned xs_base = (unsigned)__cvta_generic_to_shared(Xs);
    unsigned ws_base = (unsigned)__cvta_generic_to_shared(Ws);

    // async prologue: 16B chunks, 16 chunks per 128-half row
    for (int c = tid; c < 2048; c += 256) {
        int row = c >> 4, ch = c & 15;
        cp16(ws_base + (row * XPAD + ch * 8) * 2, W16 + row * D + ch * 8);
    }
    for (int c = tid; c < 2048; c += 256) {
        int row = c >> 4, ch = c & 15;
        int r = rowbase + row;
        if (r < n) {
            cp16(xs_base + (row * XPAD + ch * 8) * 2, Xh + (size_t)r * D + ch * 8);
        } else {
            uint4 z = make_uint4(0, 0, 0, 0);
            *(uint4*)&Xs[row * XPAD + ch * 8] = z;
        }
    }
    asm volatile("cp.async.commit_group;");
    asm volatile("cp.async.wait_group 0;" ::: "memory");
    __syncthreads();

    int warpRow = warp * 16;
    unsigned a[8][4];
#pragma unroll
    for (int ka = 0; ka < 8; ka++) {
        unsigned addr = xs_base +
            ((warpRow + (lane & 15)) * XPAD + ka * 16 + (lane >> 4) * 8) * 2;
        asm volatile("ldmatrix.sync.aligned.m8n8.x4.shared.b16 {%0,%1,%2,%3}, [%4];"
                     : "=r"(a[ka][0]), "=r"(a[ka][1]), "=r"(a[ka][2]), "=r"(a[ka][3])
                     : "r"(addr));
    }

    int g = lane >> 2;
    int c2 = (lane & 3) * 2;
    int rowLo = rowbase + warpRow + g;
    int rowHi = rowLo + 8;

    float psL = 0.f, psH = 0.f, qdL = 0.f, qdH = 0.f;

#pragma unroll
    for (int j2 = 0; j2 < 8; j2++) {
        float d0 = 0.f, d1 = 0.f, d2 = 0.f, d3 = 0.f;
        float e0 = 0.f, e1 = 0.f, e2 = 0.f, e3 = 0.f;
#pragma unroll
        for (int ka = 0; ka < 8; ka++) {
            unsigned b0, b1, b2, b3;
            unsigned baddr = ws_base +
                ((ka * 16 + (lane & 15)) * XPAD + j2 * 16 + (lane >> 4) * 8) * 2;
            LDSM_X4T(b0, b1, b2, b3, baddr);
            MMA16816(d0, d1, d2, d3, a[ka][0], a[ka][1], a[ka][2], a[ka][3], b0, b1);
            MMA16816(e0, e1, e2, e3, a[ka][0], a[ka][1], a[ka][2], a[ka][3], b2, b3);
        }
        int colA = j2 * 16 + c2;
        int colB = colA + 8;
        float avA0 = asrc[colA], avA1 = asrc[colA + 1];
        float dvA0 = adst[colA], dvA1 = adst[colA + 1];
        float avB0 = asrc[colB], avB1 = asrc[colB + 1];
        float dvB0 = adst[colB], dvB1 = adst[colB + 1];
        psL += d0 * avA0 + d1 * avA1 + e0 * avB0 + e1 * avB1;
        psH += d2 * avA0 + d3 * avA1 + e2 * avB0 + e3 * avB1;
        qdL += d0 * dvA0 + d1 * dvA1 + e0 * dvB0 + e1 * dvB1;
        qdH += d2 * dvA0 + d3 * dvA1 + e2 * dvB0 + e3 * dvB1;
        if (rowLo < n) {
            *(__half2*)&hh_out[(size_t)rowLo * D + colA] = __floats2half2_rn(d0, d1);
            *(__half2*)&hh_out[(size_t)rowLo * D + colB] = __floats2half2_rn(e0, e1);
        }
        if (rowHi < n) {
            *(__half2*)&hh_out[(size_t)rowHi * D + colA] = __floats2half2_rn(d2, d3);
            *(__half2*)&hh_out[(size_t)rowHi * D + colB] = __floats2half2_rn(e2, e3);
        }
    }

    psL += __shfl_xor_sync(0xffffffffu, psL, 1);
    psL += __shfl_xor_sync(0xffffffffu, psL, 2);
    psH += __shfl_xor_sync(0xffffffffu, psH, 1);
    psH += __shfl_xor_sync(0xffffffffu, psH, 2);
    qdL += __shfl_xor_sync(0xffffffffu, qdL, 1);
    qdL += __shfl_xor_sync(0xffffffffu, qdL, 2);
    qdH += __shfl_xor_sync(0xffffffffu, qdH, 1);
    qdH += __shfl_xor_sync(0xffffffffu, qdH, 2);
    if ((lane & 3) == 0) {
        if (rowLo < n) { g_ssrc[rowLo] = psL; g_sdst[rowLo] = qdL; }
        if (rowHi < n) { g_ssrc[rowHi] = psH; g_sdst[rowHi] = qdH; }
    }
}

// ---- layer-1: GEMM blocks + placement blocks in one launch ----
#define PLACE_EPT 4
__global__ void __launch_bounds__(256) hmma_gemm_place_kernel(
    const __half* __restrict__ Xh, const __half* __restrict__ W16,
    __half* __restrict__ hh_out,
    const float* __restrict__ asrc, const float* __restrict__ adst, int n,
    const int* __restrict__ ei, int E, int hmma_grid) {
    if ((int)blockIdx.x >= hmma_grid) {
        int pb = (int)blockIdx.x - hmma_grid;
        int i0 = (pb * 256 + (int)threadIdx.x) * PLACE_EPT;
#pragma unroll
        for (int q = 0; q < PLACE_EPT; q += 4) {
            int ib = i0 + q;
            if (ib + 3 < E && (E & 3) == 0) {
                int4 s4 = *(const int4*)&ei[ib];
                int4 r4 = *(const int4*)&g_rank[ib];
                g_esrc[g_offs[r4.x & 0xFFFF] + (r4.x >> 16)] = s4.x;
                g_esrc[g_offs[r4.y & 0xFFFF] + (r4.y >> 16)] = s4.y;
                g_esrc[g_offs[r4.z & 0xFFFF] + (r4.z >> 16)] = s4.z;
                g_esrc[g_offs[r4.w & 0xFFFF] + (r4.w >> 16)] = s4.w;
            } else {
#pragma unroll
                for (int u = 0; u < 4; u++) {
                    int i = ib + u;
                    if (i < E) {
                        int pk = g_rank[i];
                        g_esrc[g_offs[pk & 0xFFFF] + (pk >> 16)] = ei[i];
                    } else if (i < E + n) {
                        int pk = g_rank[i];
                        g_esrc[g_offs[pk & 0xFFFF] + (pk >> 16)] = i - E;
                    }
                }
            }
        }
        return;
    }
    extern __shared__ __half smh[];
    hmma_gemm_body(Xh, W16, hh_out, asrc, adst, n, blockIdx.x * 128, smh);
}

__global__ void __launch_bounds__(256) hmma_gemm_kernel(
    const __half* __restrict__ Xh, const __half* __restrict__ W16,
    __half* __restrict__ hh_out,
    const float* __restrict__ asrc, const float* __restrict__ adst, int n) {
    extern __shared__ __half smh[];
    hmma_gemm_body(Xh, W16, hh_out, asrc, adst, n, blockIdx.x * 128, smh);
}

// ---------------------------------------------------------------- HMMA output GEMM (+ counter reset)
#define WPAD 72
__global__ void __launch_bounds__(128) hmma_out_kernel(
    const __half* __restrict__ Xh, const __half* __restrict__ Wo16,
    const float* __restrict__ bias, float* __restrict__ Y, int n) {
    extern __shared__ __half smh[];
    __half* Xs = smh;                 // 64 x XPAD
    __half* Ws = smh + 64 * XPAD;     // 128 x WPAD
    int tid = threadIdx.x;
    int lane = tid & 31;
    int warp = tid >> 5;
    int rowbase = blockIdx.x * 64;

    if (blockIdx.x == 0 && tid == 0) {
        g_cnt = 0;
        g_cnt_rank = 0;
    }

    unsigned xs_base = (unsigned)__cvta_generic_to_shared(Xs);
    unsigned ws_base = (unsigned)__cvta_generic_to_shared(Ws);

    // W: 128 rows x 64 halves = 8 chunks/row (1024 chunks)
    for (int c = tid; c < 1024; c += 128) {
        int row = c >> 3, ch = c & 7;
        cp16(ws_base + (row * WPAD + ch * 8) * 2, Wo16 + row * DOUT + ch * 8);
    }
    // X: 64 rows x 128 halves = 16 chunks/row (1024 chunks)
    for (int c = tid; c < 1024; c += 128) {
        int row = c >> 4, ch = c & 15;
        int r = rowbase + row;
        if (r < n) {
            cp16(xs_base + (row * XPAD + ch * 8) * 2, Xh + (size_t)r * D + ch * 8);
        } else {
            uint4 z = make_uint4(0, 0, 0, 0);
            *(uint4*)&Xs[row * XPAD + ch * 8] = z;
        }
    }
    asm volatile("cp.async.commit_group;");
    asm volatile("cp.async.wait_group 0;" ::: "memory");
    __syncthreads();

    int warpRow = warp * 16;
    unsigned a[8][4];
#pragma unroll
    for (int ka = 0; ka < 8; ka++) {
        unsigned addr = xs_base +
            ((warpRow + (lane & 15)) * XPAD + ka * 16 + (lane >> 4) * 8) * 2;
        asm volatile("ldmatrix.sync.aligned.m8n8.x4.shared.b16 {%0,%1,%2,%3}, [%4];"
                     : "=r"(a[ka][0]), "=r"(a[ka][1]), "=r"(a[ka][2]), "=r"(a[ka][3])
                     : "r"(addr));
    }

    int g = lane >> 2;
    int c2 = (lane & 3) * 2;
    int rowLo = rowbase + warpRow + g;
    int rowHi = rowLo + 8;

#pragma unroll
    for (int j2 = 0; j2 < 4; j2++) {
        float d0 = 0.f, d1 = 0.f, d2 = 0.f, d3 = 0.f;
        float e0 = 0.f, e1 = 0.f, e2 = 0.f, e3 = 0.f;
#pragma unroll
        for (int ka = 0; ka < 8; ka++) {
            unsigned b0, b1, b2, b3;
            unsigned baddr = ws_base +
                ((ka * 16 + (lane & 15)) * WPAD + j2 * 16 + (lane >> 4) * 8) * 2;
            LDSM_X4T(b0, b1, b2, b3, baddr);
            MMA16816(d0, d1, d2, d3, a[ka][0], a[ka][1], a[ka][2], a[ka][3], b0, b1);
            MMA16816(e0, e1, e2, e3, a[ka][0], a[ka][1], a[ka][2], a[ka][3], b2, b3);
        }
        int colA = j2 * 16 + c2;
        int colB = colA + 8;
        float bA0 = bias[colA], bA1 = bias[colA + 1];
        float bB0 = bias[colB], bB1 = bias[colB + 1];
        if (rowLo < n) {
            *(float2*)&Y[(size_t)rowLo * DOUT + colA] = make_float2(d0 + bA0, d1 + bA1);
            *(float2*)&Y[(size_t)rowLo * DOUT + colB] = make_float2(e0 + bB0, e1 + bB1);
        }
        if (rowHi < n) {
            *(float2*)&Y[(size_t)rowHi * DOUT + colA] = make_float2(d2 + bA0, d3 + bA1);
            *(float2*)&Y[(size_t)rowHi * DOUT + colB] = make_float2(e2 + bB0, e3 + bB1);
        }
    }
}

// ---------------------------------------------------------------- fused alpha + aggregation
// One warp per node, edge-pair consumption. Output written as fp16 (exactly
// what the consuming GEMM would have converted to anyway).
#define CH 64
__global__ void __launch_bounds__(256, 6) gat_edge_kernel(
    const __half* __restrict__ hh, const float* __restrict__ bias,
    __half* __restrict__ out, int n, int do_relu) {
    __shared__ float2 stage[8][CH];
    int gt = blockIdx.x * blockDim.x + threadIdx.x;
    int node = gt >> 5, lane = gt & 31;
    int wslot = (threadIdx.x >> 5);
    if (node >= n) return;

    int beg = g_offs[node];
    int end = g_offs[node + 1];
    float sd = g_sdst[node];
    int h = lane >> 4;
    int lane8 = lane & 15;
    const char* hbase = (const char*)hh + lane8 * 16;

    float denom = 0.f;
    unsigned long long acc0 = 0ull, acc1 = 0ull, acc2 = 0ull, acc3 = 0ull;

    for (int cb = beg; cb < end; cb += CH) {
        int m = min(CH, end - cb);
        for (int t = lane; t < m; t += 32) {
            int s = g_esrc[cb + t];
            float ex = __expf(fmaxf(g_ssrc[s] + sd, 0.f));
            denom += ex;
            stage[wslot][t] = make_float2(__int_as_float(s << 8), ex);
        }
        if ((m & 1) && lane == 0)
            stage[wslot][m] = make_float2(stage[wslot][0].x, 0.f);
        __syncwarp();

        int mp = (m + 1) & ~1;
        int k = 0;
        for (; k + 8 <= mp; k += 8) {
            float2 p0 = stage[wslot][k + 0 + h];
            float2 p1 = stage[wslot][k + 2 + h];
            float2 p2 = stage[wslot][k + 4 + h];
            float2 p3 = stage[wslot][k + 6 + h];
            uint4 v0 = *(const uint4*)(hbase + (unsigned)__float_as_int(p0.x));
            uint4 v1 = *(const uint4*)(hbase + (unsigned)__float_as_int(p1.x));
            uint4 v2 = *(const uint4*)(hbase + (unsigned)__float_as_int(p2.x));
            uint4 v3 = *(const uint4*)(hbase + (unsigned)__float_as_int(p3.x));
#define EDGE_STEP(vv, ww) do { \
                unsigned long long w_ = dup2(ww); \
                float2 a0_ = __half22float2(*(__half2*)&(vv).x); \
                float2 a1_ = __half22float2(*(__half2*)&(vv).y); \
                float2 a2_ = __half22float2(*(__half2*)&(vv).z); \
                float2 a3_ = __half22float2(*(__half2*)&(vv).w); \
                ffma2(acc0, w_, *(unsigned long long*)&a0_); \
                ffma2(acc1, w_, *(unsigned long long*)&a1_); \
                ffma2(acc2, w_, *(unsigned long long*)&a2_); \
                ffma2(acc3, w_, *(unsigned long long*)&a3_); \
            } while (0)
            EDGE_STEP(v0, p0.y);
            EDGE_STEP(v1, p1.y);
            EDGE_STEP(v2, p2.y);
            EDGE_STEP(v3, p3.y);
        }
        for (; k < mp; k += 2) {
            float2 p = stage[wslot][k + h];
            uint4 v = *(const uint4*)(hbase + (unsigned)__float_as_int(p.x));
            EDGE_STEP(v, p.y);
        }
#undef EDGE_STEP
        __syncwarp();
    }

#pragma unroll
    for (int o = 16; o; o >>= 1) denom += __shfl_xor_sync(0xffffffffu, denom, o);
    float inv = 1.f / denom;

    float2 f0 = *(float2*)&acc0;
    float2 f1 = *(float2*)&acc1;
    float2 f2 = *(float2*)&acc2;
    float2 f3 = *(float2*)&acc3;
    f0.x += __shfl_xor_sync(0xffffffffu, f0.x, 16);
    f0.y += __shfl_xor_sync(0xffffffffu, f0.y, 16);
    f1.x += __shfl_xor_sync(0xffffffffu, f1.x, 16);
    f1.y += __shfl_xor_sync(0xffffffffu, f1.y, 16);
    f2.x += __shfl_xor_sync(0xffffffffu, f2.x, 16);
    f2.y += __shfl_xor_sync(0xffffffffu, f2.y, 16);
    f3.x += __shfl_xor_sync(0xffffffffu, f3.x, 16);
    f3.y += __shfl_xor_sync(0xffffffffu, f3.y, 16);

    if (h == 0) {
        int fb = lane8 * 8;
        float4 b0 = *(const float4*)&bias[fb];
        float4 b1 = *(const float4*)&bias[fb + 4];
        float4 o0, o1;
        o0.x = f0.x * inv + b0.x;
        o0.y = f0.y * inv + b0.y;
        o0.z = f1.x * inv + b0.z;
        o0.w = f1.y * inv + b0.w;
        o1.x = f2.x * inv + b1.x;
        o1.y = f2.y * inv + b1.y;
        o1.z = f3.x * inv + b1.z;
        o1.w = f3.y * inv + b1.w;
        if (do_relu) {
            o0.x = fmaxf(o0.x, 0.f); o0.y = fmaxf(o0.y, 0.f);
            o0.z = fmaxf(o0.z, 0.f); o0.w = fmaxf(o0.w, 0.f);
            o1.x = fmaxf(o1.x, 0.f); o1.y = fmaxf(o1.y, 0.f);
            o1.z = fmaxf(o1.z, 0.f); o1.w = fmaxf(o1.w, 0.f);
        }
        __half2 q0 = __floats2half2_rn(o0.x, o0.y);
        __half2 q1 = __floats2half2_rn(o0.z, o0.w);
        __half2 q2 = __floats2half2_rn(o1.x, o1.y);
        __half2 q3 = __floats2half2_rn(o1.z, o1.w);
        uint4 pk;
        pk.x = *(unsigned*)&q0;
        pk.y = *(unsigned*)&q1;
        pk.z = *(unsigned*)&q2;
        pk.w = *(unsigned*)&q3;
        *(uint4*)&out[(size_t)node * D + fb] = pk;
    }
}

// ---------------------------------------------------------------- launch
extern "C" void kernel_launch(void* const* d_in, const int* in_sizes, int n_in,
                              void* d_out, int out_size) {
    const float* node_x = (const float*)d_in[0];
    const int*   ei     = (const int*)d_in[1];
    const float* W1     = (const float*)d_in[2];
    const float* as1    = (const float*)d_in[3];
    const float* ad1    = (const float*)d_in[4];
    const float* b1     = (const float*)d_in[5];
    const float* W2     = (const float*)d_in[6];
    const float* as2    = (const float*)d_in[7];
    const float* ad2    = (const float*)d_in[8];
    const float* b2     = (const float*)d_in[9];
    const float* Wout   = (const float*)d_in[10];
    const float* bout   = (const float*)d_in[11];
    float* out = (float*)d_out;

    int n = in_sizes[0] / D;       // 50000
    int E = in_sizes[1] / 2;       // 1600000

    __half *hh_ptr, *xh_ptr, *nx_ptr, *w16a_ptr, *w16b_ptr, *w16o_ptr;
    cudaGetSymbolAddress((void**)&hh_ptr, g_hh);
    cudaGetSymbolAddress((void**)&xh_ptr, g_xh);
    cudaGetSymbolAddress((void**)&nx_ptr, g_nx16);
    cudaGetSymbolAddress((void**)&w16a_ptr, g_w16a);
    cudaGetSymbolAddress((void**)&w16b_ptr, g_w16b);
    cudaGetSymbolAddress((void**)&w16o_ptr, g_w16o);

    const int SMEM_HMMA = (128 * XPAD + 128 * XPAD) * (int)sizeof(__half); // ~68 KB
    const int SMEM_OUT  = (64 * XPAD + 128 * WPAD) * (int)sizeof(__half);  // ~35 KB
    cudaFuncSetAttribute(hmma_gemm_place_kernel, cudaFuncAttributeMaxDynamicSharedMemorySize, SMEM_HMMA);
    cudaFuncSetAttribute(hmma_gemm_kernel, cudaFuncAttributeMaxDynamicSharedMemorySize, SMEM_HMMA);
    cudaFuncSetAttribute(hmma_out_kernel, cudaFuncAttributeMaxDynamicSharedMemorySize, SMEM_OUT);

    int tot = E + n;
    int nb = (n + SCAN_B - 1) / SCAN_B;
    int RB = (tot + 1023) / 1024;
    int nelem4 = n * D / 4;
    int agg_grid = (n * 32 + 255) / 256;
    int hmma_grid = (n + 127) / 128;
    int out_grid = (n + 63) / 64;
    int place_blocks = (tot + 256 * PLACE_EPT - 1) / (256 * PLACE_EPT);

    // CSR rank + W/X conversion + scan, one launch
    rank_scan_kernel<<<CONV_BLOCKS + RB + nb, 256>>>(ei, E, n, W1, W2, Wout,
                                                     node_x, nelem4, RB, nb, tot);

    // layer-1 GEMM (fp16 X via cp.async) + placement merged
    hmma_gemm_place_kernel<<<hmma_grid + place_blocks, 256, SMEM_HMMA>>>(
        nx_ptr, w16a_ptr, hh_ptr, as1, ad1, n, ei, E, hmma_grid);
    gat_edge_kernel<<<agg_grid, 256>>>(hh_ptr, b1, xh_ptr, n, 1);

    // layer 2
    hmma_gemm_kernel<<<hmma_grid, 256, SMEM_HMMA>>>(xh_ptr, w16b_ptr, hh_ptr, as2, ad2, n);
    gat_edge_kernel<<<agg_grid, 256>>>(hh_ptr, b2, xh_ptr, n, 0);

    // output linear (HMMA) + counter reset for next replay
    hmma_out_kernel<<<out_grid, 128, SMEM_OUT>>>(xh_ptr, w16o_ptr, bout, out, n);
}